// round 13
// baseline (speedup 1.0000x reference)
#include <cuda_runtime.h>
#include <cuda_fp16.h>
#include <math.h>
#include <stdint.h>

// Problem constants
#define V_  50257
#define E_  256
#define H_  512
#define B_  64
#define L_  64
#define SOS_ 2

#define GR_     2048
#define KSPLIT_ 4
#define KTOT_   768
#define KPER_   (KTOT_ / KSPLIT_)   // 192

// mma logits tiling: M=64 per CTA -> 786 tiles, wave-steal balanced
#define VTC_  64
#define NBLK_ ((V_ + VTC_ - 1) / VTC_)    // 786
#define KC_   32                          // k per chunk
#define NCH_  (H_ / KC_)                  // 16

// smem stage layout (bytes): rows padded to 80B -> conflict-free ldmatrix
#define ROWB_    80
#define OFF_WHI  0
#define OFF_WLO  (64 * ROWB_)             // 5120
#define OFF_HHI  (2 * 64 * ROWB_)         // 10240
#define OFF_HLO  (3 * 64 * ROWB_)         // 15360
#define STGB_    (4 * 64 * ROWB_)         // 20480
#define SMEM_BYTES (2 * STGB_)            // 40960 (logits overlay 64*66*4=16896 fits)

#define INV2048_ 4.8828125e-4f

// ---------------- device scratch ----------------
__device__ float g_h[B_ * H_];
__device__ __align__(16) __half g_hhi[B_ * H_];
__device__ __align__(16) __half g_hlo[B_ * H_];
__device__ __align__(16) __half g_Whi[(size_t)V_ * H_];
__device__ __align__(16) __half g_Wlo[(size_t)V_ * H_];
__device__ float g_part[KSPLIT_][B_ * GR_];
__device__ unsigned long long g_amax[L_][B_];

// ---------------- helpers ----------------
__device__ __forceinline__ void cp_async16(unsigned dst, const void* src) {
    asm volatile("cp.async.cg.shared.global [%0], [%1], 16;" :: "r"(dst), "l"(src));
}
__device__ __forceinline__ void cp_async16z(unsigned dst, const void* src, int bytes) {
    asm volatile("cp.async.cg.shared.global [%0], [%1], 16, %2;"
                 :: "r"(dst), "l"(src), "r"(bytes));
}
__device__ __forceinline__ void ldm_x4(uint32_t* r, uint32_t addr) {
    asm volatile("ldmatrix.sync.aligned.m8n8.x4.shared.b16 {%0,%1,%2,%3}, [%4];"
                 : "=r"(r[0]), "=r"(r[1]), "=r"(r[2]), "=r"(r[3]) : "r"(addr));
}
__device__ __forceinline__ void mma16816(float* c, const uint32_t* a, const uint32_t* b) {
    asm volatile(
        "mma.sync.aligned.m16n8k16.row.col.f32.f16.f16.f32 "
        "{%0,%1,%2,%3}, {%4,%5,%6,%7}, {%8,%9}, {%0,%1,%2,%3};"
        : "+f"(c[0]), "+f"(c[1]), "+f"(c[2]), "+f"(c[3])
        : "r"(a[0]), "r"(a[1]), "r"(a[2]), "r"(a[3]), "r"(b[0]), "r"(b[1]));
}

// ---------------- one-time W split: fp32 -> f16 hi + f16 lo*2048 ----------------
__global__ void k_wsplit(const float* __restrict__ Wc) {
    size_t n = (size_t)V_ * H_;
    size_t stride = (size_t)gridDim.x * blockDim.x;
    for (size_t i = (size_t)blockIdx.x * blockDim.x + threadIdx.x; i < n; i += stride) {
        float x = Wc[i];
        __half hi = __float2half_rn(x);
        g_Whi[i] = hi;
        g_Wlo[i] = __float2half_rn(2048.0f * (x - __half2float(hi)));
    }
}

// ---------------- init ----------------
__global__ void k_init(const float* __restrict__ h0) {
    int stride = gridDim.x * blockDim.x;
    int i = blockIdx.x * blockDim.x + threadIdx.x;
    for (int j = i; j < B_ * H_; j += stride) {
        float x = h0[j];
        g_h[j] = x;
        __half hi = __float2half_rn(x);
        g_hhi[j] = hi;
        g_hlo[j] = __float2half_rn(2048.0f * (x - __half2float(hi)));
    }
    unsigned long long* am = &g_amax[0][0];
    for (int j = i; j < L_ * B_; j += stride) am[j] = 0ull;
}

// ---------------- gate GEMM (unchanged, verified) ----------------
__global__ __launch_bounds__(256) void k_gates_gemm(
    int t,
    const float* __restrict__ emb,
    const float* __restrict__ W_ih,
    const float* __restrict__ W_hh)
{
    int rt = blockIdx.x / KSPLIT_;
    int ks = blockIdx.x % KSPLIT_;
    int r0 = rt * 64;
    int kbase = ks * KPER_;
    int region = (r0 < 1024) ? 0 : (r0 < 1536 ? 1 : 2);

    __shared__ float As[32][68];
    __shared__ float Bs[32][68];
    __shared__ int   s_tok[B_];

    int tid = threadIdx.x;
    if (tid < B_) {
        int tok;
        if (t == 0) tok = SOS_;
        else {
            unsigned long long key = g_amax[t - 1][tid];
            tok = (int)(0xFFFFFFFFu - (unsigned)(key & 0xFFFFFFFFull));
        }
        s_tok[tid] = tok;
    }
    __syncthreads();

    int tx = tid & 15, ty = tid >> 4;
    float acc[4][4] = {};

    for (int kc = 0; kc < KPER_; kc += 32) {
        int k0 = kbase + kc;
        if (region == 1 && k0 >= E_) continue;
        if (region == 2 && k0 + 32 <= E_) continue;

        __syncthreads();
        #pragma unroll
        for (int u = 0; u < 2; u++) {
            int idx = tid * 2 + u;
            int b = idx >> 3, q = idx & 7;
            int k = k0 + q * 4;
            float4 v;
            if (k < E_) v = *(const float4*)(emb + (size_t)s_tok[b] * E_ + k);
            else        v = *(const float4*)(g_h + b * H_ + (k - E_));
            As[q * 4 + 0][b] = v.x; As[q * 4 + 1][b] = v.y;
            As[q * 4 + 2][b] = v.z; As[q * 4 + 3][b] = v.w;
        }
        #pragma unroll
        for (int u = 0; u < 2; u++) {
            int idx = tid * 2 + u;
            int rr = idx >> 3, q = idx & 7;
            int k = k0 + q * 4;
            int r = r0 + rr;
            float4 v;
            if (region == 0) {
                if (k < E_) v = *(const float4*)(W_ih + (size_t)r * E_ + k);
                else        v = *(const float4*)(W_hh + (size_t)r * H_ + (k - E_));
            } else if (region == 1) {
                v = *(const float4*)(W_ih + (size_t)r * E_ + k);
            } else {
                v = *(const float4*)(W_hh + (size_t)(r - 512) * H_ + (k - E_));
            }
            Bs[q * 4 + 0][rr] = v.x; Bs[q * 4 + 1][rr] = v.y;
            Bs[q * 4 + 2][rr] = v.z; Bs[q * 4 + 3][rr] = v.w;
        }
        __syncthreads();

        #pragma unroll
        for (int k = 0; k < 32; k++) {
            float a[4], w[4];
            *(float4*)a = *(const float4*)&As[k][ty * 4];
            *(float4*)w = *(const float4*)&Bs[k][tx * 4];
            #pragma unroll
            for (int i = 0; i < 4; i++)
                #pragma unroll
                for (int j = 0; j < 4; j++)
                    acc[i][j] = fmaf(a[i], w[j], acc[i][j]);
        }
    }

    float* outp = &g_part[ks][0];
    #pragma unroll
    for (int i = 0; i < 4; i++) {
        int b = ty * 4 + i;
        #pragma unroll
        for (int j = 0; j < 4; j++) {
            int r = r0 + tx * 4 + j;
            outp[b * GR_ + r] = acc[i][j];
        }
    }
}

// ---------------- gate nonlinearity + hidden update + f16 split ----------------
__global__ __launch_bounds__(256) void k_gates_elem(
    const float* __restrict__ b_ih, const float* __restrict__ b_hh)
{
    int i = blockIdx.x * blockDim.x + threadIdx.x;
    if (i >= B_ * H_) return;
    int b = i >> 9;
    int j = i & 511;

    float sr = 0.f, sz = 0.f, in_ = 0.f, hn = 0.f;
    #pragma unroll
    for (int s = 0; s < KSPLIT_; s++) {
        const float* row = &g_part[s][b * GR_];
        sr  += row[j];
        sz  += row[512 + j];
        in_ += row[1024 + j];
        hn  += row[1536 + j];
    }
    sr  += b_ih[j] + b_hh[j];
    sz  += b_ih[512 + j] + b_hh[512 + j];
    in_ += b_ih[1024 + j];
    hn  += b_hh[1024 + j];

    float r = 1.f / (1.f + expf(-sr));
    float z = 1.f / (1.f + expf(-sz));
    float n = tanhf(in_ + r * hn);
    float h = (1.f - z) * n + z * g_h[i];
    g_h[i] = h;
    __half hi = __float2half_rn(h);
    g_hhi[i] = hi;
    g_hlo[i] = __float2half_rn(2048.0f * (h - __half2float(hi)));
}

// ---------------- classifier logits on HMMA + fused argmax, M=64 tiles ----------------
// Per CTA: D[64 v, 64 b] = W[64,512] @ h[64,512]^T, f16 2-split, fp32 regs.
// 8 warps: wm = wid>>1 (v tile of 16, 1 mt), wn = wid&1 (b half of 32, 4 nt).
// Both A [m][k] and B [n][k] k-contiguous -> non-trans ldmatrix for both.
// accA = hi*hi; accB = hi*lo + lo*hi (lo pre-scaled by 2048); D = accA + accB/2048.
__global__ __launch_bounds__(256, 2) void k_logits_mma(
    int t,
    const float* __restrict__ bc,
    float* __restrict__ out)
{
    extern __shared__ unsigned char smraw[];
    __shared__ unsigned long long s_best[4][64];

    int tid = threadIdx.x;
    int wid = tid >> 5, lane = tid & 31;
    int wm = wid >> 1, wn = wid & 1;
    int v0 = blockIdx.x * VTC_;

    uint32_t smem = (uint32_t)__cvta_generic_to_shared(smraw);

    // ---- stage loader: 1024 x 16B cp.async, exactly 4 per thread ----
    auto load_stage = [&](int st, int kc) {
        uint32_t base = smem + st * STGB_;
        #pragma unroll
        for (int u = 0; u < 4; u++) {
            int idx = tid + u * 256;
            int row = (idx & 255) >> 2, c = idx & 3;
            if (idx < 256) {                      // W hi
                int vg = v0 + row;
                cp_async16z(base + OFF_WHI + row * ROWB_ + c * 16,
                            g_Whi + (size_t)(vg < V_ ? vg : 0) * H_ + kc + c * 8,
                            (vg < V_) ? 16 : 0);
            } else if (idx < 512) {               // W lo
                int vg = v0 + row;
                cp_async16z(base + OFF_WLO + row * ROWB_ + c * 16,
                            g_Wlo + (size_t)(vg < V_ ? vg : 0) * H_ + kc + c * 8,
                            (vg < V_) ? 16 : 0);
            } else if (idx < 768) {               // h hi
                cp_async16(base + OFF_HHI + row * ROWB_ + c * 16,
                           g_hhi + row * H_ + kc + c * 8);
            } else {                              // h lo
                cp_async16(base + OFF_HLO + row * ROWB_ + c * 16,
                           g_hlo + row * H_ + kc + c * 8);
            }
        }
    };

    float accA[4][4] = {};
    float accB[4][4] = {};

    // ldmatrix lane-invariant offsets (non-trans both)
    int lmat = lane >> 3, lr = lane & 7;
    // A frag mats {m0-7/k0-7, m8-15/k0-7, m0-7/k8-15, m8-15/k8-15}
    uint32_t aoff = (uint32_t)((wm * 16 + (lmat & 1) * 8 + lr) * ROWB_ + ((lmat >> 1) * 8) * 2);
    // B frag mats {n0-7/k0-7, n0-7/k8-15, n8-15/k0-7, n8-15/k8-15}
    uint32_t boff = (uint32_t)((wn * 32 + (lmat >> 1) * 8 + lr) * ROWB_ + ((lmat & 1) * 8) * 2);

    load_stage(0, 0);
    asm volatile("cp.async.commit_group;");

    #pragma unroll 1
    for (int s = 0; s < NCH_; s++) {
        asm volatile("cp.async.wait_group 0;");
        __syncthreads();
        if (s + 1 < NCH_) {
            load_stage((s + 1) & 1, (s + 1) * KC_);
            asm volatile("cp.async.commit_group;");
        }

        uint32_t base = smem + (s & 1) * STGB_;
        uint32_t aWhi = base + OFF_WHI + aoff;
        uint32_t aWlo = base + OFF_WLO + aoff;
        uint32_t bHhi = base + OFF_HHI + boff;
        uint32_t bHlo = base + OFF_HLO + boff;

        #pragma unroll
        for (int ks = 0; ks < 32; ks += 16) {
            uint32_t ahi[4], alo[4], bhi[2][4], blo[2][4];
            ldm_x4(ahi, aWhi + ks * 2);
            ldm_x4(alo, aWlo + ks * 2);
            #pragma unroll
            for (int ng = 0; ng < 2; ng++) {
                ldm_x4(bhi[ng], bHhi + ng * (16 * ROWB_) + ks * 2);
                ldm_x4(blo[ng], bHlo + ng * (16 * ROWB_) + ks * 2);
            }
            #pragma unroll
            for (int nt = 0; nt < 4; nt++) {
                const uint32_t* bh = &bhi[nt >> 1][2 * (nt & 1)];
                const uint32_t* bl = &blo[nt >> 1][2 * (nt & 1)];
                mma16816(accA[nt], ahi, bh);
                mma16816(accB[nt], ahi, bl);
                mma16816(accB[nt], alo, bh);
            }
        }
        __syncthreads();
    }

    // ---- epilogue: combine, stash to smem [v][66], bias+store, argmax ----
    float* sL = (float*)smraw;           // overlay: 64*66*4 = 16896 <= 40960
    int qrow = lane >> 2, qcol = 2 * (lane & 3);
    #pragma unroll
    for (int nt = 0; nt < 4; nt++) {
        int v = wm * 16 + qrow;
        int b = wn * 32 + nt * 8 + qcol;
        float x0 = accA[nt][0] + accB[nt][0] * INV2048_;
        float x1 = accA[nt][1] + accB[nt][1] * INV2048_;
        float x2 = accA[nt][2] + accB[nt][2] * INV2048_;
        float x3 = accA[nt][3] + accB[nt][3] * INV2048_;
        *(float2*)&sL[v * 66 + b] = make_float2(x0, x1);
        *(float2*)&sL[(v + 8) * 66 + b] = make_float2(x2, x3);
    }
    __syncthreads();

    // bias + coalesced global store (each thread: fixed v = tid&63, 16 b's)
    {
        int v = tid & 63;
        int vg = v0 + v;
        float* outt = out + (size_t)t * B_ * V_;
        if (vg < V_) {
            float bcv = bc[vg];
            #pragma unroll
            for (int u = 0; u < 16; u++) {
                int b = (tid >> 6) + 4 * u;
                float x = sL[v * 66 + b] + bcv;
                sL[v * 66 + b] = x;
                outt[(size_t)b * V_ + vg] = x;
            }
        }
    }
    __syncthreads();

    // argmax: b = tid&63, part = tid>>6 scans 16 v-rows
    {
        int b = tid & 63, part = tid >> 6;
        unsigned long long best = 0ull;
        #pragma unroll 4
        for (int i = 0; i < 16; i++) {
            int v = part * 16 + i;
            int vg = v0 + v;
            if (vg < V_) {
                float l = sL[v * 66 + b];
                unsigned u = __float_as_uint(l);
                u = (u & 0x80000000u) ? ~u : (u | 0x80000000u);
                unsigned long long key =
                    ((unsigned long long)u << 32) |
                    (unsigned long long)(0xFFFFFFFFu - (unsigned)vg);
                if (key > best) best = key;
            }
        }
        s_best[part][b] = best;
    }
    __syncthreads();
    if (tid < 64) {
        unsigned long long m = s_best[0][tid];
        if (s_best[1][tid] > m) m = s_best[1][tid];
        if (s_best[2][tid] > m) m = s_best[2][tid];
        if (s_best[3][tid] > m) m = s_best[3][tid];
        if (m) atomicMax(&g_amax[t][tid], m);
    }
}

// ---------------- launch ----------------
extern "C" void kernel_launch(void* const* d_in, const int* in_sizes, int n_in,
                              void* d_out, int out_size) {
    const float* h0   = (const float*)d_in[0];
    const float* emb  = (const float*)d_in[1];
    const float* W_ih = (const float*)d_in[2];
    const float* W_hh = (const float*)d_in[3];
    const float* b_ih = (const float*)d_in[4];
    const float* b_hh = (const float*)d_in[5];
    const float* Wc   = (const float*)d_in[6];
    const float* bc   = (const float*)d_in[7];
    float* out = (float*)d_out;

    cudaFuncSetAttribute(k_logits_mma, cudaFuncAttributeMaxDynamicSharedMemorySize,
                         SMEM_BYTES);

    k_wsplit<<<512, 256>>>(Wc);
    k_init<<<32, 256>>>(h0);
    int gemm_blocks = (GR_ / 64) * KSPLIT_;   // 128
    int elem_blocks = (B_ * H_) / 256;        // 128
    for (int t = 0; t < L_; t++) {
        k_gates_gemm<<<gemm_blocks, 256>>>(t, emb, W_ih, W_hh);
        k_gates_elem<<<elem_blocks, 256>>>(b_ih, b_hh);
        k_logits_mma<<<NBLK_, 256, SMEM_BYTES>>>(t, bc, out);
    }
}

// round 14
// speedup vs baseline: 1.1915x; 1.1915x over previous
#include <cuda_runtime.h>
#include <cuda_fp16.h>
#include <math.h>
#include <stdint.h>

// Problem constants
#define V_  50257
#define E_  256
#define H_  512
#define B_  64
#define L_  64
#define SOS_ 2

#define GR_     2048
#define KSPLIT_ 4
#define KTOT_   768
#define KPER_   (KTOT_ / KSPLIT_)   // 192

// mma logits tiling: M=176 per CTA -> 286 tiles = ONE wave at occ 2
#define VTC_  176
#define NMT_  11                          // m16-tiles per CTA
#define NBLK_ ((V_ + VTC_ - 1) / VTC_)    // 286
#define KC_   32
#define NCH_  (H_ / KC_)                  // 16

// smem stage layout (bytes): rows padded to 80B -> conflict-free ldmatrix
#define ROWB_    80
#define OFF_WHI  0
#define OFF_WLO  (176 * ROWB_)            // 14080
#define OFF_HHI  (2 * 176 * ROWB_)        // 28160
#define OFF_HLO  (OFF_HHI + 64 * ROWB_)   // 33280
#define STGB_    (OFF_HLO + 64 * ROWB_)   // 38400
#define SMEM_BYTES (2 * STGB_)            // 76800 (logits overlay 176*66*4=46464 fits)

#define INV2048_ 4.8828125e-4f

// ---------------- device scratch ----------------
__device__ float g_h[B_ * H_];
__device__ __align__(16) __half g_hhi[B_ * H_];
__device__ __align__(16) __half g_hlo[B_ * H_];
__device__ __align__(16) __half g_Whi[(size_t)V_ * H_];
__device__ __align__(16) __half g_Wlo[(size_t)V_ * H_];
__device__ float g_part[KSPLIT_][B_ * GR_];
__device__ unsigned long long g_amax[L_][B_];

// ---------------- helpers ----------------
__device__ __forceinline__ void cp_async16(unsigned dst, const void* src) {
    asm volatile("cp.async.cg.shared.global [%0], [%1], 16;" :: "r"(dst), "l"(src));
}
__device__ __forceinline__ void cp_async16z(unsigned dst, const void* src, int bytes) {
    asm volatile("cp.async.cg.shared.global [%0], [%1], 16, %2;"
                 :: "r"(dst), "l"(src), "r"(bytes));
}
__device__ __forceinline__ void ldm_x4(uint32_t* r, uint32_t addr) {
    asm volatile("ldmatrix.sync.aligned.m8n8.x4.shared.b16 {%0,%1,%2,%3}, [%4];"
                 : "=r"(r[0]), "=r"(r[1]), "=r"(r[2]), "=r"(r[3]) : "r"(addr));
}
__device__ __forceinline__ void mma16816(float* c, const uint32_t* a, const uint32_t* b) {
    asm volatile(
        "mma.sync.aligned.m16n8k16.row.col.f32.f16.f16.f32 "
        "{%0,%1,%2,%3}, {%4,%5,%6,%7}, {%8,%9}, {%0,%1,%2,%3};"
        : "+f"(c[0]), "+f"(c[1]), "+f"(c[2]), "+f"(c[3])
        : "r"(a[0]), "r"(a[1]), "r"(a[2]), "r"(a[3]), "r"(b[0]), "r"(b[1]));
}

// ---------------- one-time W split: fp32 -> f16 hi + f16 lo*2048 ----------------
__global__ void k_wsplit(const float* __restrict__ Wc) {
    size_t n = (size_t)V_ * H_;
    size_t stride = (size_t)gridDim.x * blockDim.x;
    for (size_t i = (size_t)blockIdx.x * blockDim.x + threadIdx.x; i < n; i += stride) {
        float x = Wc[i];
        __half hi = __float2half_rn(x);
        g_Whi[i] = hi;
        g_Wlo[i] = __float2half_rn(2048.0f * (x - __half2float(hi)));
    }
}

// ---------------- init ----------------
__global__ void k_init(const float* __restrict__ h0) {
    int stride = gridDim.x * blockDim.x;
    int i = blockIdx.x * blockDim.x + threadIdx.x;
    for (int j = i; j < B_ * H_; j += stride) {
        float x = h0[j];
        g_h[j] = x;
        __half hi = __float2half_rn(x);
        g_hhi[j] = hi;
        g_hlo[j] = __float2half_rn(2048.0f * (x - __half2float(hi)));
    }
    unsigned long long* am = &g_amax[0][0];
    for (int j = i; j < L_ * B_; j += stride) am[j] = 0ull;
}

// ---------------- gate GEMM (unchanged, verified) ----------------
__global__ __launch_bounds__(256) void k_gates_gemm(
    int t,
    const float* __restrict__ emb,
    const float* __restrict__ W_ih,
    const float* __restrict__ W_hh)
{
    int rt = blockIdx.x / KSPLIT_;
    int ks = blockIdx.x % KSPLIT_;
    int r0 = rt * 64;
    int kbase = ks * KPER_;
    int region = (r0 < 1024) ? 0 : (r0 < 1536 ? 1 : 2);

    __shared__ float As[32][68];
    __shared__ float Bs[32][68];
    __shared__ int   s_tok[B_];

    int tid = threadIdx.x;
    if (tid < B_) {
        int tok;
        if (t == 0) tok = SOS_;
        else {
            unsigned long long key = g_amax[t - 1][tid];
            tok = (int)(0xFFFFFFFFu - (unsigned)(key & 0xFFFFFFFFull));
        }
        s_tok[tid] = tok;
    }
    __syncthreads();

    int tx = tid & 15, ty = tid >> 4;
    float acc[4][4] = {};

    for (int kc = 0; kc < KPER_; kc += 32) {
        int k0 = kbase + kc;
        if (region == 1 && k0 >= E_) continue;
        if (region == 2 && k0 + 32 <= E_) continue;

        __syncthreads();
        #pragma unroll
        for (int u = 0; u < 2; u++) {
            int idx = tid * 2 + u;
            int b = idx >> 3, q = idx & 7;
            int k = k0 + q * 4;
            float4 v;
            if (k < E_) v = *(const float4*)(emb + (size_t)s_tok[b] * E_ + k);
            else        v = *(const float4*)(g_h + b * H_ + (k - E_));
            As[q * 4 + 0][b] = v.x; As[q * 4 + 1][b] = v.y;
            As[q * 4 + 2][b] = v.z; As[q * 4 + 3][b] = v.w;
        }
        #pragma unroll
        for (int u = 0; u < 2; u++) {
            int idx = tid * 2 + u;
            int rr = idx >> 3, q = idx & 7;
            int k = k0 + q * 4;
            int r = r0 + rr;
            float4 v;
            if (region == 0) {
                if (k < E_) v = *(const float4*)(W_ih + (size_t)r * E_ + k);
                else        v = *(const float4*)(W_hh + (size_t)r * H_ + (k - E_));
            } else if (region == 1) {
                v = *(const float4*)(W_ih + (size_t)r * E_ + k);
            } else {
                v = *(const float4*)(W_hh + (size_t)(r - 512) * H_ + (k - E_));
            }
            Bs[q * 4 + 0][rr] = v.x; Bs[q * 4 + 1][rr] = v.y;
            Bs[q * 4 + 2][rr] = v.z; Bs[q * 4 + 3][rr] = v.w;
        }
        __syncthreads();

        #pragma unroll
        for (int k = 0; k < 32; k++) {
            float a[4], w[4];
            *(float4*)a = *(const float4*)&As[k][ty * 4];
            *(float4*)w = *(const float4*)&Bs[k][tx * 4];
            #pragma unroll
            for (int i = 0; i < 4; i++)
                #pragma unroll
                for (int j = 0; j < 4; j++)
                    acc[i][j] = fmaf(a[i], w[j], acc[i][j]);
        }
    }

    float* outp = &g_part[ks][0];
    #pragma unroll
    for (int i = 0; i < 4; i++) {
        int b = ty * 4 + i;
        #pragma unroll
        for (int j = 0; j < 4; j++) {
            int r = r0 + tx * 4 + j;
            outp[b * GR_ + r] = acc[i][j];
        }
    }
}

// ---------------- gate nonlinearity + hidden update + f16 split ----------------
__global__ __launch_bounds__(256) void k_gates_elem(
    const float* __restrict__ b_ih, const float* __restrict__ b_hh)
{
    int i = blockIdx.x * blockDim.x + threadIdx.x;
    if (i >= B_ * H_) return;
    int b = i >> 9;
    int j = i & 511;

    float sr = 0.f, sz = 0.f, in_ = 0.f, hn = 0.f;
    #pragma unroll
    for (int s = 0; s < KSPLIT_; s++) {
        const float* row = &g_part[s][b * GR_];
        sr  += row[j];
        sz  += row[512 + j];
        in_ += row[1024 + j];
        hn  += row[1536 + j];
    }
    sr  += b_ih[j] + b_hh[j];
    sz  += b_ih[512 + j] + b_hh[512 + j];
    in_ += b_ih[1024 + j];
    hn  += b_hh[1024 + j];

    float r = 1.f / (1.f + expf(-sr));
    float z = 1.f / (1.f + expf(-sz));
    float n = tanhf(in_ + r * hn);
    float h = (1.f - z) * n + z * g_h[i];
    g_h[i] = h;
    __half hi = __float2half_rn(h);
    g_hhi[i] = hi;
    g_hlo[i] = __float2half_rn(2048.0f * (h - __half2float(hi)));
}

// ---------------- classifier logits on HMMA + fused argmax, M=176 single wave ----
// Per CTA: D[176 v, 64 b] = W[176,512] @ h[64,512]^T, f16 2-split, fp32 regs.
// 8 warps: wn = wid&1 (b half of 32, 4 nt); wm = wid>>1 owns m16-tiles
// {wm, wm+4, wm+8 (if wm<3)}. A-frags loaded per-m-tile (keeps regs <= 128).
// accA = hi*hi; accB = hi*lo + lo*hi (lo pre-scaled 2048); D = accA + accB/2048.
__global__ __launch_bounds__(256, 2) void k_logits_mma(
    int t,
    const float* __restrict__ bc,
    float* __restrict__ out)
{
    extern __shared__ unsigned char smraw[];
    __shared__ unsigned long long s_best[4][64];

    int tid = threadIdx.x;
    int wid = tid >> 5, lane = tid & 31;
    int wm = wid >> 1, wn = wid & 1;
    int v0 = blockIdx.x * VTC_;

    uint32_t smem = (uint32_t)__cvta_generic_to_shared(smraw);

    // ---- stage loader: 1920 x 16B cp.async (Whi 704, Wlo 704, hhi 256, hlo 256)
    auto load_stage = [&](int st, int kc) {
        uint32_t base = smem + st * STGB_;
        #pragma unroll
        for (int u = 0; u < 8; u++) {
            int idx = tid + u * 256;
            if (idx < 704) {                      // W hi
                int row = idx >> 2, c = idx & 3;
                int vg = v0 + row;
                cp_async16z(base + OFF_WHI + row * ROWB_ + c * 16,
                            g_Whi + (size_t)(vg < V_ ? vg : 0) * H_ + kc + c * 8,
                            (vg < V_) ? 16 : 0);
            } else if (idx < 1408) {              // W lo
                int i2 = idx - 704;
                int row = i2 >> 2, c = i2 & 3;
                int vg = v0 + row;
                cp_async16z(base + OFF_WLO + row * ROWB_ + c * 16,
                            g_Wlo + (size_t)(vg < V_ ? vg : 0) * H_ + kc + c * 8,
                            (vg < V_) ? 16 : 0);
            } else if (idx < 1664) {              // h hi
                int i2 = idx - 1408;
                int row = i2 >> 2, c = i2 & 3;
                cp_async16(base + OFF_HHI + row * ROWB_ + c * 16,
                           g_hhi + row * H_ + kc + c * 8);
            } else if (idx < 1920) {              // h lo
                int i2 = idx - 1664;
                int row = i2 >> 2, c = i2 & 3;
                cp_async16(base + OFF_HLO + row * ROWB_ + c * 16,
                           g_hlo + row * H_ + kc + c * 8);
            }
        }
    };

    int mcount = (wm < 3) ? 3 : 2;
    float accA[3][4][4] = {};
    float accB[3][4][4] = {};

    // ldmatrix lane-invariant offsets (non-trans both operands)
    int lmat = lane >> 3, lr = lane & 7;
    // A frag mats {m0-7/k0-7, m8-15/k0-7, m0-7/k8-15, m8-15/k8-15}
    uint32_t aoffs[3];
    #pragma unroll
    for (int mi = 0; mi < 3; mi++) {
        int mt = wm + mi * 4;                     // m16-tile index (mi==2 only if wm<3)
        aoffs[mi] = (uint32_t)((mt * 16 + (lmat & 1) * 8 + lr) * ROWB_
                               + ((lmat >> 1) * 8) * 2);
    }
    // B frag mats {n0-7/k0-7, n0-7/k8-15, n8-15/k0-7, n8-15/k8-15}
    uint32_t boff = (uint32_t)((wn * 32 + (lmat >> 1) * 8 + lr) * ROWB_
                               + ((lmat & 1) * 8) * 2);

    load_stage(0, 0);
    asm volatile("cp.async.commit_group;");

    #pragma unroll 1
    for (int s = 0; s < NCH_; s++) {
        asm volatile("cp.async.wait_group 0;");
        __syncthreads();
        if (s + 1 < NCH_) {
            load_stage((s + 1) & 1, (s + 1) * KC_);
            asm volatile("cp.async.commit_group;");
        }

        uint32_t base = smem + (s & 1) * STGB_;
        uint32_t bHhi = base + OFF_HHI + boff;
        uint32_t bHlo = base + OFF_HLO + boff;

        #pragma unroll
        for (int ks = 0; ks < 32; ks += 16) {
            uint32_t bhi[2][4], blo[2][4];
            #pragma unroll
            for (int ng = 0; ng < 2; ng++) {
                ldm_x4(bhi[ng], bHhi + ng * (16 * ROWB_) + ks * 2);
                ldm_x4(blo[ng], bHlo + ng * (16 * ROWB_) + ks * 2);
            }
            #pragma unroll
            for (int mi = 0; mi < 3; mi++) {
                if (mi < mcount) {
                    uint32_t ahi[4], alo[4];
                    ldm_x4(ahi, base + OFF_WHI + aoffs[mi] + ks * 2);
                    ldm_x4(alo, base + OFF_WLO + aoffs[mi] + ks * 2);
                    #pragma unroll
                    for (int nt = 0; nt < 4; nt++) {
                        const uint32_t* bh = &bhi[nt >> 1][2 * (nt & 1)];
                        const uint32_t* bl = &blo[nt >> 1][2 * (nt & 1)];
                        mma16816(accA[mi][nt], ahi, bh);
                        mma16816(accB[mi][nt], ahi, bl);
                        mma16816(accB[mi][nt], alo, bh);
                    }
                }
            }
        }
        __syncthreads();
    }

    // ---- epilogue: combine, stash to smem [v][66], bias+store, argmax ----
    float* sL = (float*)smraw;           // overlay: 176*66*4 = 46464 <= 76800
    int qrow = lane >> 2, qcol = 2 * (lane & 3);
    #pragma unroll
    for (int mi = 0; mi < 3; mi++) {
        if (mi < mcount) {
            int vbase = (wm + mi * 4) * 16 + qrow;
            #pragma unroll
            for (int nt = 0; nt < 4; nt++) {
                int b = wn * 32 + nt * 8 + qcol;
                float x0 = accA[mi][nt][0] + accB[mi][nt][0] * INV2048_;
                float x1 = accA[mi][nt][1] + accB[mi][nt][1] * INV2048_;
                float x2 = accA[mi][nt][2] + accB[mi][nt][2] * INV2048_;
                float x3 = accA[mi][nt][3] + accB[mi][nt][3] * INV2048_;
                *(float2*)&sL[vbase * 66 + b] = make_float2(x0, x1);
                *(float2*)&sL[(vbase + 8) * 66 + b] = make_float2(x2, x3);
            }
        }
    }
    __syncthreads();

    // bias + coalesced global store
    {
        float* outt = out + (size_t)t * B_ * V_;
        for (int v = tid; v < VTC_; v += 256) {
            int vg = v0 + v;
            if (vg < V_) {
                float bcv = bc[vg];
                #pragma unroll
                for (int b = 0; b < B_; b++) {
                    float x = sL[v * 66 + b] + bcv;
                    sL[v * 66 + b] = x;
                    outt[(size_t)b * V_ + vg] = x;
                }
            }
        }
    }
    __syncthreads();

    // argmax: b = tid&63, part = tid>>6 scans 44 v-rows
    {
        int b = tid & 63, part = tid >> 6;
        unsigned long long best = 0ull;
        #pragma unroll 4
        for (int i = 0; i < 44; i++) {
            int v = part * 44 + i;
            int vg = v0 + v;
            if (vg < V_) {
                float l = sL[v * 66 + b];
                unsigned u = __float_as_uint(l);
                u = (u & 0x80000000u) ? ~u : (u | 0x80000000u);
                unsigned long long key =
                    ((unsigned long long)u << 32) |
                    (unsigned long long)(0xFFFFFFFFu - (unsigned)vg);
                if (key > best) best = key;
            }
        }
        s_best[part][b] = best;
    }
    __syncthreads();
    if (tid < 64) {
        unsigned long long m = s_best[0][tid];
        if (s_best[1][tid] > m) m = s_best[1][tid];
        if (s_best[2][tid] > m) m = s_best[2][tid];
        if (s_best[3][tid] > m) m = s_best[3][tid];
        if (m) atomicMax(&g_amax[t][tid], m);
    }
}

// ---------------- launch ----------------
extern "C" void kernel_launch(void* const* d_in, const int* in_sizes, int n_in,
                              void* d_out, int out_size) {
    const float* h0   = (const float*)d_in[0];
    const float* emb  = (const float*)d_in[1];
    const float* W_ih = (const float*)d_in[2];
    const float* W_hh = (const float*)d_in[3];
    const float* b_ih = (const float*)d_in[4];
    const float* b_hh = (const float*)d_in[5];
    const float* Wc   = (const float*)d_in[6];
    const float* bc   = (const float*)d_in[7];
    float* out = (float*)d_out;

    cudaFuncSetAttribute(k_logits_mma, cudaFuncAttributeMaxDynamicSharedMemorySize,
                         SMEM_BYTES);

    k_wsplit<<<512, 256>>>(Wc);
    k_init<<<32, 256>>>(h0);
    int gemm_blocks = (GR_ / 64) * KSPLIT_;   // 128
    int elem_blocks = (B_ * H_) / 256;        // 128
    for (int t = 0; t < L_; t++) {
        k_gates_gemm<<<gemm_blocks, 256>>>(t, emb, W_ih, W_hh);
        k_gates_elem<<<elem_blocks, 256>>>(b_ih, b_hh);
        k_logits_mma<<<NBLK_, 256, SMEM_BYTES>>>(t, bc, out);
    }
}